// round 12
// baseline (speedup 1.0000x reference)
#include <cuda_runtime.h>
#include <cuda_fp16.h>
#include <cstdint>
#include <math.h>

#define B_  64
#define T_  1024
#define E_  512
#define A_  128
#define NF_ 32
#define K_  31
#define SEG_ 32

// ---------------- smem layout for energies kernel (dynamic) ----------------
#define OFF_A32_0 0              // 32KB fp32 A chunk buf0
#define OFF_A32_1 32768          // 32KB fp32 A chunk buf1
#define OFF_A16_0 65536          // 16KB fp16 A tile buf0
#define OFF_A16_1 81920
#define OFF_B0    98304          // 16KB fp16 B tile buf0
#define OFF_B1    114688
#define OFF_AWC   131072         // 2048 floats
#define OFF_PQ    139264         // 128 floats
#define OFF_V     139776         // 128 floats
#define OFF_PART  140288         // 512 floats
#define OFF_TIDX  142336         // 128 ints
#define SMEM_TOTAL 142848

// ---------------- scratch ----------------
__device__ float g_pq[B_*A_];
__device__ float g_energies[B_*T_];
__device__ __align__(16) __half g_wmh[A_*E_];     // fp16(Wm)
__device__ __align__(16) __half g_wclh[A_*64];    // fp16(folded Wl@conv_w)
__device__ __align__(16) float g_cpart[SEG_*B_*E_];
__device__ int g_cnt[B_];
__device__ int g_tidx[B_*T_];

// ---------------- helpers ----------------
__device__ __forceinline__ uint32_t smem_u32(const void* p) {
    uint32_t a;
    asm("{ .reg .u64 t; cvta.to.shared.u64 t, %1; cvt.u32.u64 %0, t; }" : "=r"(a) : "l"(p));
    return a;
}
#define STS128(addr, a, b, c, d) \
    asm volatile("st.shared.v4.b32 [%0], {%1,%2,%3,%4};" :: "r"(addr), "r"(a), "r"(b), "r"(c), "r"(d) : "memory")
#define CPASYNC16(dst, src) \
    asm volatile("cp.async.ca.shared.global [%0], [%1], 16;" :: "r"(dst), "l"(src) : "memory")
#define CPCOMMIT() asm volatile("cp.async.commit_group;" ::: "memory")

__device__ __forceinline__ void ldsm_x4(uint32_t (&r)[4], uint32_t addr) {
    asm volatile("ldmatrix.sync.aligned.m8n8.x4.shared.b16 {%0,%1,%2,%3}, [%4];"
        : "=r"(r[0]), "=r"(r[1]), "=r"(r[2]), "=r"(r[3]) : "r"(addr));
}
__device__ __forceinline__ void mma_f16(float (&c)[4], const uint32_t (&a)[4],
                                        uint32_t b0, uint32_t b1) {
    asm volatile("mma.sync.aligned.m16n8k16.row.col.f32.f16.f16.f32 "
        "{%0,%1,%2,%3}, {%4,%5,%6,%7}, {%8,%9}, {%0,%1,%2,%3};"
        : "+f"(c[0]), "+f"(c[1]), "+f"(c[2]), "+f"(c[3])
        : "r"(a[0]), "r"(a[1]), "r"(a[2]), "r"(a[3]), "r"(b0), "r"(b1));
}
__device__ __forceinline__ uint32_t tile_addr(uint32_t base, int row, int kbyte) {
    uint32_t off = (uint32_t)(row*128 + kbyte);
    return base + (off ^ ((off >> 3) & 0x70));
}
__device__ __forceinline__ uint32_t ldsm_addr(uint32_t base, int rb, int kb, int lane) {
    int row = rb + (lane & 15);
    int kbyte = (kb + (lane >> 4)*8)*2;
    return tile_addr(base, row, kbyte);
}
__device__ __forceinline__ uint32_t pack2h(float a, float b) {
    __half2 p = __halves2half2(__float2half_rn(a), __float2half_rn(b));
    return *reinterpret_cast<uint32_t*>(&p);
}
__device__ __forceinline__ float tanh_fast(float x) {
    float e = __expf(fminf(fmaxf(2.f*x, -30.f), 30.f));
    return 1.f - __fdividef(2.f, e + 1.f);
}
__device__ __forceinline__ float locval(const float* s_awc, int tor, int j) {
    if (j >= 62) return 0.f;
    int c = (j >= 31) ? 1 : 0;
    int k = j - c*31;
    int t = tor - 15 + k;
    return (t >= 0 && t < T_) ? s_awc[c*T_ + t] : 0.f;
}

// ---------------- prep kernels (split so energies is the 4th launch) ----------------
__global__ __launch_bounds__(256)
void compact_kernel(const int* __restrict__ mask) {
    const int b = blockIdx.x, tid = threadIdx.x;
    __shared__ int s1[256], s2[256];
    int loc[4]; int c = 0;
    #pragma unroll
    for (int q = 0; q < 4; q++) {
        int t = tid*4 + q;
        if (mask[b*T_ + t] == 0) loc[c++] = t;
    }
    s1[tid] = c; __syncthreads();
    int* src = s1; int* dst = s2;
    #pragma unroll
    for (int off = 1; off < 256; off <<= 1) {
        int vv = src[tid];
        if (tid >= off) vv += src[tid - off];
        dst[tid] = vv;
        __syncthreads();
        int* tmp = src; src = dst; dst = tmp;
    }
    int base = src[tid] - c;
    for (int i = 0; i < c; i++) g_tidx[b*T_ + base + i] = loc[i];
    if (tid == 255) g_cnt[b] = src[255];
}

// blocks 0..63: pq; blocks 64..127: Wm fp16 convert
__global__ __launch_bounds__(256)
void prep2_kernel(const float* __restrict__ ahs, const float* __restrict__ Wq,
                  const float* __restrict__ Wm)
{
    __shared__ float sh[A_];
    const int blk = blockIdx.x, tid = threadIdx.x;
    if (blk < 64) {
        const int b = blk;
        if (tid < A_) sh[tid] = ahs[b*A_ + tid];
        __syncthreads();
        if (tid < A_) {
            const float* wr = Wq + tid*A_;
            float s = 0.f;
            #pragma unroll 8
            for (int i = 0; i < A_; i++) s += sh[i]*wr[i];
            g_pq[b*A_ + tid] = s;
        }
    } else {
        const int i0 = (blk - 64)*1024 + tid*4;
        float4 x = *(const float4*)(Wm + i0);
        uint2 w;
        w.x = pack2h(x.x, x.y);
        w.y = pack2h(x.z, x.w);
        *reinterpret_cast<uint2*>(g_wmh + i0) = w;
    }
}

__global__ __launch_bounds__(256)
void wcl_kernel(const float* __restrict__ Wl, const float* __restrict__ convw) {
    __shared__ float sWl[A_*NF_];
    __shared__ float sCv[NF_*62];
    const int base_j = blockIdx.x*16;
    const int tid = threadIdx.x;
    for (int i = tid; i < A_*NF_; i += 256) sWl[i] = Wl[i];
    for (int i = tid; i < NF_*62; i += 256) sCv[i] = convw[i];
    __syncthreads();
    #pragma unroll
    for (int it = 0; it < 8; it++) {
        int idx = it*256 + tid;
        int jj = idx >> 7, a = idx & 127;
        int j = base_j + jj;
        if (j < 64) {
            float s = 0.f;
            if (j < 62) {
                #pragma unroll
                for (int f = 0; f < NF_; f++) s += sWl[a*NF_ + f]*sCv[f*62 + j];
            }
            g_wclh[a*64 + j] = __float2half_rn(s);
        }
    }
}

// ---------------- energies: cp.async fp32-A staged HMMA pipeline ----------------
// Per chunk: A32 fp32 chunk (32KB) and B fp16 tile (16KB) are cp.async'd one full
// chunk ahead (double-buffered). Convert phase reads A32 from smem (each thread
// reads exactly the bytes it copied -> no cross-thread sync needed), packs fp16,
// STS to swizzled A16. Critical path = convert + MMA; DRAM fully async.
__global__ __launch_bounds__(256, 1)
void energies_mma_kernel(const float* __restrict__ pmem,
                         const float* __restrict__ awc,
                         const float* __restrict__ v)
{
    extern __shared__ char smem[];
    const uint32_t sb = smem_u32(smem);
    const int tid = threadIdx.x;
    const int wid = tid >> 5, lane = tid & 31;
    const int b = blockIdx.y, t0 = blockIdx.x*128;
    const int cnt = g_cnt[b];
    if (t0 >= cnt) return;
    const int warp_m = wid & 1, warp_n = wid >> 1;
    const int mb = warp_m*64, nb = warp_n*32;

    float* s_awc  = (float*)(smem + OFF_AWC);
    float* s_pq   = (float*)(smem + OFF_PQ);
    float* s_v    = (float*)(smem + OFF_V);
    float* s_part = (float*)(smem + OFF_PART);
    int*   s_tidx = (int*)(smem + OFF_TIDX);

    // ---- metadata (s_tidx needed before cp.async source addresses) ----
    if (tid < 128) {
        int t = (t0 + tid < cnt) ? g_tidx[b*T_ + t0 + tid] : 0;
        s_tidx[tid] = t;
    }
    for (int i = tid; i < 2*T_; i += 256) s_awc[i] = awc[(size_t)b*2*T_ + i];
    if (tid < A_) { s_pq[tid] = g_pq[b*A_ + tid]; s_v[tid] = v[tid]; }
    __syncthreads();

    // per-thread row for staging/convert: r = (tid>>3) + 32*it, g = tid&7
    const int gcol = tid & 7;
    const float* rowsrc[4];
    #pragma unroll
    for (int it = 0; it < 4; it++) {
        int r = (tid >> 3) + 32*it;
        rowsrc[it] = pmem + ((size_t)b*T_ + s_tidx[r])*E_ + gcol*8;
    }

    // ---- prolog: issue groups for chunks 0 and 1 ----
    #pragma unroll
    for (int c0 = 0; c0 < 2; c0++) {
        const uint32_t dA32 = sb + (c0 ? OFF_A32_1 : OFF_A32_0);
        const uint32_t dB   = sb + (c0 ? OFF_B1 : OFF_B0);
        #pragma unroll
        for (int it = 0; it < 4; it++) {
            int r = (tid >> 3) + 32*it;
            uint32_t dst = dA32 + (uint32_t)(r*256 + gcol*32);
            CPASYNC16(dst,      (const void*)(rowsrc[it] + c0*64));
            CPASYNC16(dst + 16, (const void*)(rowsrc[it] + c0*64 + 4));
        }
        #pragma unroll
        for (int it = 0; it < 4; it++) {
            int idx = tid + 256*it, r = idx >> 3, g = idx & 7;
            CPASYNC16(tile_addr(dB, r, g*16), (const void*)(g_wmh + (size_t)r*E_ + c0*64 + g*8));
        }
        CPCOMMIT();
    }

    float acc[4][4][4];
    #pragma unroll
    for (int i = 0; i < 4; i++)
        #pragma unroll
        for (int j = 0; j < 4; j++)
            #pragma unroll
            for (int q = 0; q < 4; q++) acc[i][j][q] = 0.f;

    for (int ch = 0; ch < 9; ch++) {
        const int p = ch & 1;
        const uint32_t baseA32 = sb + (p ? OFF_A32_1 : OFF_A32_0);
        const uint32_t baseA16 = sb + (p ? OFF_A16_1 : OFF_A16_0);
        const uint32_t baseB   = sb + (p ? OFF_B1 : OFF_B0);

        // ---- wait for chunk ch's group (keep ch+1 in flight) ----
        if (ch < 8) asm volatile("cp.async.wait_group 1;" ::: "memory");
        else        asm volatile("cp.async.wait_group 0;" ::: "memory");

        // ---- convert -> A16[p] ----
        if (ch < 8) {
            #pragma unroll
            for (int it = 0; it < 4; it++) {
                int r = (tid >> 3) + 32*it;
                const float4* src = (const float4*)(smem + (baseA32 - sb) + r*256 + gcol*32);
                float4 x0 = src[0], x1 = src[1];
                STS128(tile_addr(baseA16, r, gcol*16),
                       pack2h(x0.x, x0.y), pack2h(x0.z, x0.w),
                       pack2h(x1.x, x1.y), pack2h(x1.z, x1.w));
            }
        } else {
            const int r = tid >> 1, jb = (tid & 1)*32;
            const int tor = s_tidx[r];
            #pragma unroll
            for (int jj = 0; jj < 32; jj += 8) {
                uint32_t hw[4];
                #pragma unroll
                for (int q = 0; q < 4; q++) {
                    int j0 = jb + jj + 2*q;
                    hw[q] = pack2h(locval(s_awc, tor, j0), locval(s_awc, tor, j0 + 1));
                }
                STS128(tile_addr(baseA16, r, (jb + jj)*2), hw[0], hw[1], hw[2], hw[3]);
            }
        }
        __syncthreads();     // A16[p], B[p] visible to all warps

        // ---- MMA chunk ch ----
        #pragma unroll
        for (int ks = 0; ks < 4; ks++) {
            const int kb = ks*16;
            uint32_t ah[4][4], bf[2][4];
            #pragma unroll
            for (int i = 0; i < 4; i++)
                ldsm_x4(ah[i], ldsm_addr(baseA16, mb + 16*i, kb, lane));
            #pragma unroll
            for (int j2 = 0; j2 < 2; j2++)
                ldsm_x4(bf[j2], ldsm_addr(baseB, nb + 16*j2, kb, lane));
            #pragma unroll
            for (int i = 0; i < 4; i++) {
                #pragma unroll
                for (int j = 0; j < 4; j++) {
                    const int j2 = j >> 1, jo = j & 1;
                    mma_f16(acc[i][j], ah[i], bf[j2][jo], bf[j2][jo+2]);
                }
            }
        }

        // ---- refill buffers p with chunk ch+2 (after all reads of p done) ----
        if (ch + 2 <= 8) {
            __syncthreads();     // B[p]/A16[p] reads complete before overwrite
            const int chn = ch + 2;
            if (chn < 8) {
                #pragma unroll
                for (int it = 0; it < 4; it++) {
                    int r = (tid >> 3) + 32*it;
                    uint32_t dst = baseA32 + (uint32_t)(r*256 + gcol*32);
                    CPASYNC16(dst,      (const void*)(rowsrc[it] + chn*64));
                    CPASYNC16(dst + 16, (const void*)(rowsrc[it] + chn*64 + 4));
                }
                #pragma unroll
                for (int it = 0; it < 4; it++) {
                    int idx = tid + 256*it, r = idx >> 3, g = idx & 7;
                    CPASYNC16(tile_addr(baseB, r, g*16),
                              (const void*)(g_wmh + (size_t)r*E_ + chn*64 + g*8));
                }
            } else {
                // chunk 8: only B (location weights); A comes from s_awc
                #pragma unroll
                for (int it = 0; it < 4; it++) {
                    int idx = tid + 256*it, r = idx >> 3, g = idx & 7;
                    CPASYNC16(tile_addr(baseB, r, g*16),
                              (const void*)(g_wclh + (size_t)r*64 + g*8));
                }
            }
            CPCOMMIT();
        } else if (ch < 8) {
            __syncthreads();     // keep buffer lifetime discipline for last iters
        }
    }

    // ---- epilogue ----
    #pragma unroll
    for (int i = 0; i < 4; i++) {
        #pragma unroll
        for (int half = 0; half < 2; half++) {
            float s = 0.f;
            #pragma unroll
            for (int j = 0; j < 4; j++) {
                const int a0 = nb + j*8 + (lane & 3)*2;
                float x0 = acc[i][j][half*2+0] + s_pq[a0];
                float x1 = acc[i][j][half*2+1] + s_pq[a0+1];
                s += s_v[a0]*tanh_fast(x0) + s_v[a0+1]*tanh_fast(x1);
            }
            s += __shfl_xor_sync(0xffffffffu, s, 1);
            s += __shfl_xor_sync(0xffffffffu, s, 2);
            if ((lane & 3) == 0) {
                int row = mb + i*16 + (lane >> 2) + half*8;
                s_part[row*4 + warp_n] = s;
            }
        }
    }
    __syncthreads();
    if (tid < 128 && t0 + tid < cnt) {
        const float* pp = s_part + tid*4;
        g_energies[(size_t)b*T_ + s_tidx[tid]] = (pp[0] + pp[1]) + (pp[2] + pp[3]);
    }
}

// ---------------- masked softmax over T ----------------
__global__ void softmax_kernel(const int* __restrict__ mask, float* __restrict__ wout) {
    const int b = blockIdx.x, tid = threadIdx.x;
    __shared__ float red[256];
    float e[4];
    float mx = -INFINITY;
    #pragma unroll
    for (int q = 0; q < 4; q++) {
        int t = tid + 256*q;
        float ev = g_energies[b*T_ + t];
        if (mask[b*T_ + t] != 0) ev = -INFINITY;
        e[q] = ev;
        mx = fmaxf(mx, ev);
    }
    red[tid] = mx; __syncthreads();
    for (int s = 128; s > 0; s >>= 1) {
        if (tid < s) red[tid] = fmaxf(red[tid], red[tid + s]);
        __syncthreads();
    }
    const float m = red[0];
    __syncthreads();
    float ex[4], sum = 0.f;
    #pragma unroll
    for (int q = 0; q < 4; q++) {
        ex[q] = (e[q] == -INFINITY) ? 0.f : expf(e[q] - m);
        sum += ex[q];
    }
    red[tid] = sum; __syncthreads();
    for (int s = 128; s > 0; s >>= 1) {
        if (tid < s) red[tid] += red[tid + s];
        __syncthreads();
    }
    const float inv = 1.f / red[0];
    #pragma unroll
    for (int q = 0; q < 4; q++) wout[b*T_ + tid + 256*q] = ex[q]*inv;
}

// ---------------- context: 32 segs, full E row per CTA, LDG.64 ----------------
__global__ __launch_bounds__(256)
void context_part_kernel(const float* __restrict__ mem,
                         const float* __restrict__ w)
{
    __shared__ float sw[32];
    __shared__ int sti[32];
    const int seg = blockIdx.x, b = blockIdx.y;
    const int tid = threadIdx.x;
    const int cnt = g_cnt[b];
    const int base = seg*32;

    if (tid < 32) {
        int ci = base + tid;
        int t = (ci < cnt) ? g_tidx[b*T_ + ci] : 0;
        sti[tid] = t;
        sw[tid] = (ci < cnt) ? w[b*T_ + t] : 0.f;
    }
    __syncthreads();

    int rows = cnt - base;
    rows = rows < 0 ? 0 : (rows > 32 ? 32 : rows);

    const float2* mb = (const float2*)(mem + (size_t)b*T_*E_) + tid;
    float2 a0 = {0.f, 0.f}, a1 = {0.f, 0.f}, a2 = {0.f, 0.f}, a3 = {0.f, 0.f};
    int t = 0;
    for (; t + 8 <= rows; t += 8) {
        float2 m0 = mb[(size_t)sti[t  ]*(E_/2)];
        float2 m1 = mb[(size_t)sti[t+1]*(E_/2)];
        float2 m2 = mb[(size_t)sti[t+2]*(E_/2)];
        float2 m3 = mb[(size_t)sti[t+3]*(E_/2)];
        float2 m4 = mb[(size_t)sti[t+4]*(E_/2)];
        float2 m5 = mb[(size_t)sti[t+5]*(E_/2)];
        float2 m6 = mb[(size_t)sti[t+6]*(E_/2)];
        float2 m7 = mb[(size_t)sti[t+7]*(E_/2)];
        a0.x += sw[t  ]*m0.x; a0.y += sw[t  ]*m0.y;
        a1.x += sw[t+1]*m1.x; a1.y += sw[t+1]*m1.y;
        a2.x += sw[t+2]*m2.x; a2.y += sw[t+2]*m2.y;
        a3.x += sw[t+3]*m3.x; a3.y += sw[t+3]*m3.y;
        a0.x += sw[t+4]*m4.x; a0.y += sw[t+4]*m4.y;
        a1.x += sw[t+5]*m5.x; a1.y += sw[t+5]*m5.y;
        a2.x += sw[t+6]*m6.x; a2.y += sw[t+6]*m6.y;
        a3.x += sw[t+7]*m7.x; a3.y += sw[t+7]*m7.y;
    }
    for (; t < rows; t++) {
        float2 m0 = mb[(size_t)sti[t]*(E_/2)];
        a0.x += sw[t]*m0.x; a0.y += sw[t]*m0.y;
    }
    float2 r;
    r.x = (a0.x + a1.x) + (a2.x + a3.x);
    r.y = (a0.y + a1.y) + (a2.y + a3.y);
    *((float2*)(g_cpart + ((size_t)seg*B_ + b)*E_) + tid) = r;
}

// ---------------- reduce over 32 segs, float4 ----------------
__global__ void context_reduce_kernel(float* __restrict__ ctx) {
    const int i4 = blockIdx.x*256 + threadIdx.x;     // over B*E/4
    float4 s = {0.f, 0.f, 0.f, 0.f};
    #pragma unroll
    for (int seg = 0; seg < SEG_; seg++) {
        float4 p = *((const float4*)(g_cpart + (size_t)seg*B_*E_) + i4);
        s.x += p.x; s.y += p.y; s.z += p.z; s.w += p.w;
    }
    *((float4*)ctx + i4) = s;
}

// ---------------- launch ----------------
extern "C" void kernel_launch(void* const* d_in, const int* in_sizes, int n_in,
                              void* d_out, int out_size)
{
    const float* ahs   = (const float*)d_in[0];   // [B, A]
    const float* mem   = (const float*)d_in[1];   // [B, T, E]
    const float* pmem  = (const float*)d_in[2];   // [B, T, E]
    const float* awc   = (const float*)d_in[3];   // [B, 2, T]
    const int*   mask  = (const int*)d_in[4];     // [B, T] bool -> int32
    const float* Wq    = (const float*)d_in[5];   // [A, A]
    const float* Wm    = (const float*)d_in[6];   // [A, E]
    const float* v     = (const float*)d_in[7];   // [1, A]
    const float* convw = (const float*)d_in[8];   // [NF, 2, K]
    const float* Wl    = (const float*)d_in[9];   // [A, NF]

    float* out_ctx = (float*)d_out;            // [B, E]
    float* out_w   = (float*)d_out + B_*E_;    // [B, T]

    cudaFuncSetAttribute(energies_mma_kernel,
                         cudaFuncAttributeMaxDynamicSharedMemorySize, SMEM_TOTAL);

    compact_kernel<<<B_, 256>>>(mask);                      // launch 1
    prep2_kernel<<<128, 256>>>(ahs, Wq, Wm);                // launch 2
    wcl_kernel<<<4, 256>>>(Wl, convw);                      // launch 3
    energies_mma_kernel<<<dim3(T_/128, B_), 256, SMEM_TOTAL>>>(pmem, awc, v);  // launch 4 (ncu target)
    softmax_kernel<<<B_, 256>>>(mask, out_w);               // launch 5
    context_part_kernel<<<dim3(SEG_, B_), 256>>>(mem, out_w);
    context_reduce_kernel<<<(B_*E_/4)/256, 256>>>(out_ctx);
}

// round 13
// speedup vs baseline: 1.1442x; 1.1442x over previous
#include <cuda_runtime.h>
#include <cuda_fp16.h>
#include <cstdint>
#include <math.h>

#define B_  64
#define T_  1024
#define E_  512
#define A_  128
#define NF_ 32
#define K_  31
#define SEG_ 32

// ---------------- smem layout for energies kernel (dynamic) ----------------
#define OFF_A16_0 0              // 8KB fp16 A tile (64 rows x 64 cols)
#define OFF_A16_1 8192
#define OFF_B0    16384          // 16KB fp16 B tile (128 rows x 64 cols)
#define OFF_B1    32768
#define OFF_AWC   49152          // 2048 floats
#define OFF_PQ    57344          // 128 floats
#define OFF_V     57856          // 128 floats
#define OFF_PART  58368          // 256 floats
#define OFF_TIDX  59392          // 64 ints
#define SMEM_TOTAL 59648

// ---------------- scratch ----------------
__device__ float g_pq[B_*A_];
__device__ float g_energies[B_*T_];
__device__ __align__(16) __half g_wmh[A_*E_];     // fp16(Wm)
__device__ __align__(16) __half g_wclh[A_*64];    // fp16(folded Wl@conv_w)
__device__ __align__(16) float g_cpart[SEG_*B_*E_];
__device__ int g_cnt[B_];
__device__ int g_tidx[B_*T_];

// ---------------- helpers ----------------
__device__ __forceinline__ uint32_t smem_u32(const void* p) {
    uint32_t a;
    asm("{ .reg .u64 t; cvta.to.shared.u64 t, %1; cvt.u32.u64 %0, t; }" : "=r"(a) : "l"(p));
    return a;
}
#define STS128(addr, a, b, c, d) \
    asm volatile("st.shared.v4.b32 [%0], {%1,%2,%3,%4};" :: "r"(addr), "r"(a), "r"(b), "r"(c), "r"(d) : "memory")
#define CPASYNC16(dst, src) \
    asm volatile("cp.async.ca.shared.global [%0], [%1], 16;" :: "r"(dst), "l"(src) : "memory")
#define CPCOMMIT() asm volatile("cp.async.commit_group;" ::: "memory")

__device__ __forceinline__ void ldsm_x4(uint32_t (&r)[4], uint32_t addr) {
    asm volatile("ldmatrix.sync.aligned.m8n8.x4.shared.b16 {%0,%1,%2,%3}, [%4];"
        : "=r"(r[0]), "=r"(r[1]), "=r"(r[2]), "=r"(r[3]) : "r"(addr));
}
__device__ __forceinline__ void mma_f16(float (&c)[4], const uint32_t (&a)[4],
                                        uint32_t b0, uint32_t b1) {
    asm volatile("mma.sync.aligned.m16n8k16.row.col.f32.f16.f16.f32 "
        "{%0,%1,%2,%3}, {%4,%5,%6,%7}, {%8,%9}, {%0,%1,%2,%3};"
        : "+f"(c[0]), "+f"(c[1]), "+f"(c[2]), "+f"(c[3])
        : "r"(a[0]), "r"(a[1]), "r"(a[2]), "r"(a[3]), "r"(b0), "r"(b1));
}
__device__ __forceinline__ uint32_t tile_addr(uint32_t base, int row, int kbyte) {
    uint32_t off = (uint32_t)(row*128 + kbyte);
    return base + (off ^ ((off >> 3) & 0x70));
}
__device__ __forceinline__ uint32_t ldsm_addr(uint32_t base, int rb, int kb, int lane) {
    int row = rb + (lane & 15);
    int kbyte = (kb + (lane >> 4)*8)*2;
    return tile_addr(base, row, kbyte);
}
__device__ __forceinline__ uint32_t pack2h(float a, float b) {
    __half2 p = __halves2half2(__float2half_rn(a), __float2half_rn(b));
    return *reinterpret_cast<uint32_t*>(&p);
}
__device__ __forceinline__ float tanh_fast(float x) {
    float e = __expf(fminf(fmaxf(2.f*x, -30.f), 30.f));
    return 1.f - __fdividef(2.f, e + 1.f);
}
__device__ __forceinline__ float locval(const float* s_awc, int tor, int j) {
    if (j >= 62) return 0.f;
    int c = (j >= 31) ? 1 : 0;
    int k = j - c*31;
    int t = tor - 15 + k;
    return (t >= 0 && t < T_) ? s_awc[c*T_ + t] : 0.f;
}

// ---------------- fused prep kernel ----------------
__global__ __launch_bounds__(256)
void prep_kernel(const int* __restrict__ mask,
                 const float* __restrict__ ahs, const float* __restrict__ Wq,
                 const float* __restrict__ Wm,
                 const float* __restrict__ Wl, const float* __restrict__ convw)
{
    __shared__ float smf[6144];
    const int blk = blockIdx.x, tid = threadIdx.x;

    if (blk < 64) {
        const int b = blk;
        int* s1 = (int*)smf;
        int* s2 = s1 + 256;
        int loc[4]; int c = 0;
        #pragma unroll
        for (int q = 0; q < 4; q++) {
            int t = tid*4 + q;
            if (mask[b*T_ + t] == 0) loc[c++] = t;
        }
        s1[tid] = c; __syncthreads();
        int* src = s1; int* dst = s2;
        #pragma unroll
        for (int off = 1; off < 256; off <<= 1) {
            int vv = src[tid];
            if (tid >= off) vv += src[tid - off];
            dst[tid] = vv;
            __syncthreads();
            int* tmp = src; src = dst; dst = tmp;
        }
        int base = src[tid] - c;
        for (int i = 0; i < c; i++) g_tidx[b*T_ + base + i] = loc[i];
        if (tid == 255) g_cnt[b] = src[255];
    } else if (blk < 128) {
        const int b = blk - 64;
        float* sh = smf;
        if (tid < A_) sh[tid] = ahs[b*A_ + tid];
        __syncthreads();
        if (tid < A_) {
            const float* wr = Wq + tid*A_;
            float s = 0.f;
            #pragma unroll 8
            for (int i = 0; i < A_; i++) s += sh[i]*wr[i];
            g_pq[b*A_ + tid] = s;
        }
    } else if (blk < 192) {
        const int i0 = (blk - 128)*1024 + tid*4;
        float4 x = *(const float4*)(Wm + i0);
        uint2 w;
        w.x = pack2h(x.x, x.y);
        w.y = pack2h(x.z, x.w);
        *reinterpret_cast<uint2*>(g_wmh + i0) = w;
    } else {
        const int base_j = (blk - 192)*16;
        float* sWl = smf;                  // [128][32]
        float* sCv = smf + 4096;           // [32][62]
        for (int i = tid; i < A_*NF_; i += 256) sWl[i] = Wl[i];
        for (int i = tid; i < NF_*62; i += 256) sCv[i] = convw[i];
        __syncthreads();
        #pragma unroll
        for (int it = 0; it < 8; it++) {
            int idx = it*256 + tid;
            int jj = idx >> 7, a = idx & 127;
            int j = base_j + jj;
            if (j < 64) {
                float s = 0.f;
                if (j < 62) {
                    #pragma unroll
                    for (int f = 0; f < NF_; f++) s += sWl[a*NF_ + f]*sCv[f*62 + j];
                }
                g_wclh[a*64 + j] = __float2half_rn(s);
            }
        }
    }
}

// ---------------- HMMA energies: 64-row tiles, 2 CTAs/SM, reg-prefetch pipeline ----------------
// CTA = (b, 64 compacted-t rows). 8 warps: warp_m = wid&1 (32 rows), warp_n = wid>>1 (32 cols).
__global__ __launch_bounds__(256, 2)
void energies_mma_kernel(const float* __restrict__ pmem,
                         const float* __restrict__ awc,
                         const float* __restrict__ v)
{
    extern __shared__ char smem[];
    const uint32_t sb = smem_u32(smem);
    const int tid = threadIdx.x;
    const int wid = tid >> 5, lane = tid & 31;
    const int b = blockIdx.y, t0 = blockIdx.x*64;
    const int cnt = g_cnt[b];
    if (t0 >= cnt) return;
    const int warp_m = wid & 1, warp_n = wid >> 1;
    const int mb = warp_m*32, nb = warp_n*32;

    float* s_awc  = (float*)(smem + OFF_AWC);
    float* s_pq   = (float*)(smem + OFF_PQ);
    float* s_v    = (float*)(smem + OFF_V);
    float* s_part = (float*)(smem + OFF_PART);
    int*   s_tidx = (int*)(smem + OFF_TIDX);

    // cp.async B(0): 128 rows x 64 cols fp16
    #pragma unroll
    for (int it = 0; it < 4; it++) {
        int idx = tid + 256*it, r2 = idx >> 3, g = idx & 7;
        CPASYNC16(tile_addr(sb + OFF_B0, r2, g*16), (const void*)(g_wmh + (size_t)r2*E_ + g*8));
    }
    CPCOMMIT();

    if (tid < 64) {
        int t = (t0 + tid < cnt) ? g_tidx[b*T_ + t0 + tid] : 0;
        s_tidx[tid] = t;
    }
    for (int i = tid; i < 2*T_; i += 256) s_awc[i] = awc[(size_t)b*2*T_ + i];
    if (tid < A_) { s_pq[tid] = g_pq[b*A_ + tid]; s_v[tid] = v[tid]; }
    __syncthreads();

    // staging geometry: r = tid>>2 (64 rows), g4 = tid&3 (16-float group)
    const int r = tid >> 2, g4 = tid & 3;
    const float* rowsrc = pmem + ((size_t)b*T_ + s_tidx[r])*E_ + g4*16;

    float acc[2][4][4];
    #pragma unroll
    for (int i = 0; i < 2; i++)
        #pragma unroll
        for (int j = 0; j < 4; j++)
            #pragma unroll
            for (int q = 0; q < 4; q++) acc[i][j][q] = 0.f;

    // prefetch A(0): 16 floats per thread
    float4 pf[4];
    #pragma unroll
    for (int q = 0; q < 4; q++) pf[q] = ((const float4*)rowsrc)[q];

    for (int ch = 0; ch < 9; ch++) {
        const int p = ch & 1;
        const uint32_t baseA = sb + (p ? OFF_A16_1 : OFF_A16_0);
        const uint32_t baseB = sb + (p ? OFF_B1 : OFF_B0);

        // ---- convert + STS A(ch) ----
        if (ch < 8) {
            uint32_t h[8];
            #pragma unroll
            for (int q = 0; q < 4; q++) {
                h[2*q]   = pack2h(pf[q].x, pf[q].y);
                h[2*q+1] = pack2h(pf[q].z, pf[q].w);
            }
            STS128(tile_addr(baseA, r, g4*32),      h[0], h[1], h[2], h[3]);
            STS128(tile_addr(baseA, r, g4*32 + 16), h[4], h[5], h[6], h[7]);
        } else {
            const int tor = s_tidx[r];
            uint32_t hw[8];
            #pragma unroll
            for (int q = 0; q < 8; q++) {
                int j0 = g4*16 + 2*q;
                hw[q] = pack2h(locval(s_awc, tor, j0), locval(s_awc, tor, j0 + 1));
            }
            STS128(tile_addr(baseA, r, g4*32),      hw[0], hw[1], hw[2], hw[3]);
            STS128(tile_addr(baseA, r, g4*32 + 16), hw[4], hw[5], hw[6], hw[7]);
        }

        // ---- issue next-chunk loads (B via cp.async, A via LDG prefetch) ----
        if (ch < 8) {
            const uint32_t baseBn = sb + ((ch & 1) ? OFF_B0 : OFF_B1);
            if (ch + 1 < 8) {
                const int e0n = (ch + 1)*64;
                #pragma unroll
                for (int it = 0; it < 4; it++) {
                    int idx = tid + 256*it, r2 = idx >> 3, g = idx & 7;
                    CPASYNC16(tile_addr(baseBn, r2, g*16),
                              (const void*)(g_wmh + (size_t)r2*E_ + e0n + g*8));
                }
                CPCOMMIT();
                #pragma unroll
                for (int q = 0; q < 4; q++) pf[q] = ((const float4*)(rowsrc + e0n))[q];
            } else {
                #pragma unroll
                for (int it = 0; it < 4; it++) {
                    int idx = tid + 256*it, r2 = idx >> 3, g = idx & 7;
                    CPASYNC16(tile_addr(baseBn, r2, g*16),
                              (const void*)(g_wclh + (size_t)r2*64 + g*8));
                }
                CPCOMMIT();
            }
            asm volatile("cp.async.wait_group 1;" ::: "memory");
        } else {
            asm volatile("cp.async.wait_group 0;" ::: "memory");
        }
        __syncthreads();

        // ---- MMA: 4 k16 steps x (2 m-frags x 4 n-frags) ----
        #pragma unroll
        for (int ks = 0; ks < 4; ks++) {
            const int kb = ks*16;
            uint32_t ah[2][4], bf[2][4];
            #pragma unroll
            for (int i = 0; i < 2; i++)
                ldsm_x4(ah[i], ldsm_addr(baseA, mb + 16*i, kb, lane));
            #pragma unroll
            for (int j2 = 0; j2 < 2; j2++)
                ldsm_x4(bf[j2], ldsm_addr(baseB, nb + 16*j2, kb, lane));
            #pragma unroll
            for (int i = 0; i < 2; i++) {
                #pragma unroll
                for (int j = 0; j < 4; j++) {
                    const int j2 = j >> 1, jo = j & 1;
                    mma_f16(acc[i][j], ah[i], bf[j2][jo], bf[j2][jo+2]);
                }
            }
        }
        if (ch < 8) __syncthreads();
    }

    // ---- epilogue ----
    #pragma unroll
    for (int i = 0; i < 2; i++) {
        #pragma unroll
        for (int half = 0; half < 2; half++) {
            float s = 0.f;
            #pragma unroll
            for (int j = 0; j < 4; j++) {
                const int a0 = nb + j*8 + (lane & 3)*2;
                float x0 = acc[i][j][half*2+0] + s_pq[a0];
                float x1 = acc[i][j][half*2+1] + s_pq[a0+1];
                s += s_v[a0]*tanh_fast(x0) + s_v[a0+1]*tanh_fast(x1);
            }
            s += __shfl_xor_sync(0xffffffffu, s, 1);
            s += __shfl_xor_sync(0xffffffffu, s, 2);
            if ((lane & 3) == 0) {
                int row = mb + i*16 + (lane >> 2) + half*8;
                s_part[row*4 + warp_n] = s;
            }
        }
    }
    __syncthreads();
    if (tid < 64 && t0 + tid < cnt) {
        const float* pp = s_part + tid*4;
        g_energies[(size_t)b*T_ + s_tidx[tid]] = (pp[0] + pp[1]) + (pp[2] + pp[3]);
    }
}

// ---------------- masked softmax over T ----------------
__global__ void softmax_kernel(const int* __restrict__ mask, float* __restrict__ wout) {
    const int b = blockIdx.x, tid = threadIdx.x;
    __shared__ float red[256];
    float e[4];
    float mx = -INFINITY;
    #pragma unroll
    for (int q = 0; q < 4; q++) {
        int t = tid + 256*q;
        float ev = g_energies[b*T_ + t];
        if (mask[b*T_ + t] != 0) ev = -INFINITY;
        e[q] = ev;
        mx = fmaxf(mx, ev);
    }
    red[tid] = mx; __syncthreads();
    for (int s = 128; s > 0; s >>= 1) {
        if (tid < s) red[tid] = fmaxf(red[tid], red[tid + s]);
        __syncthreads();
    }
    const float m = red[0];
    __syncthreads();
    float ex[4], sum = 0.f;
    #pragma unroll
    for (int q = 0; q < 4; q++) {
        ex[q] = (e[q] == -INFINITY) ? 0.f : expf(e[q] - m);
        sum += ex[q];
    }
    red[tid] = sum; __syncthreads();
    for (int s = 128; s > 0; s >>= 1) {
        if (tid < s) red[tid] += red[tid + s];
        __syncthreads();
    }
    const float inv = 1.f / red[0];
    #pragma unroll
    for (int q = 0; q < 4; q++) wout[b*T_ + tid + 256*q] = ex[q]*inv;
}

// ---------------- context: 32 segs, float4 gathers, 2 row-groups ----------------
__global__ __launch_bounds__(256)
void context_part_kernel(const float* __restrict__ mem,
                         const float* __restrict__ w)
{
    __shared__ float sw[32];
    __shared__ int sti[32];
    __shared__ float4 spart[128];
    const int seg = blockIdx.x, b = blockIdx.y;
    const int tid = threadIdx.x;
    const int cnt = g_cnt[b];
    const int base = seg*32;

    if (tid < 32) {
        int ci = base + tid;
        int t = (ci < cnt) ? g_tidx[b*T_ + ci] : 0;
        sti[tid] = t;
        sw[tid] = (ci < cnt) ? w[b*T_ + t] : 0.f;
    }
    __syncthreads();

    int rows = cnt - base;
    rows = rows < 0 ? 0 : (rows > 32 ? 32 : rows);

    const int h = tid >> 7, c = tid & 127;             // group, float4 column
    const float4* mb4 = (const float4*)(mem + (size_t)b*T_*E_) + c;
    float4 a0 = {0,0,0,0}, a1 = {0,0,0,0}, a2 = {0,0,0,0}, a3 = {0,0,0,0};
    int t = h;
    for (; t + 6 < rows; t += 8) {                     // rows t, t+2, t+4, t+6 for this group
        float4 m0 = mb4[(size_t)sti[t  ]*(E_/4)];
        float4 m1 = mb4[(size_t)sti[t+2]*(E_/4)];
        float4 m2 = mb4[(size_t)sti[t+4]*(E_/4)];
        float4 m3 = mb4[(size_t)sti[t+6]*(E_/4)];
        float w0 = sw[t], w1 = sw[t+2], w2 = sw[t+4], w3 = sw[t+6];
        a0.x += w0*m0.x; a0.y += w0*m0.y; a0.z += w0*m0.z; a0.w += w0*m0.w;
        a1.x += w1*m1.x; a1.y += w1*m1.y; a1.z += w1*m1.z; a1.w += w1*m1.w;
        a2.x += w2*m2.x; a2.y += w2*m2.y; a2.z += w2*m2.z; a2.w += w2*m2.w;
        a3.x += w3*m3.x; a3.y += w3*m3.y; a3.z += w3*m3.z; a3.w += w3*m3.w;
    }
    for (; t < rows; t += 2) {
        float4 m0 = mb4[(size_t)sti[t]*(E_/4)];
        float w0 = sw[t];
        a0.x += w0*m0.x; a0.y += w0*m0.y; a0.z += w0*m0.z; a0.w += w0*m0.w;
    }
    float4 aa;
    aa.x = (a0.x + a1.x) + (a2.x + a3.x);
    aa.y = (a0.y + a1.y) + (a2.y + a3.y);
    aa.z = (a0.z + a1.z) + (a2.z + a3.z);
    aa.w = (a0.w + a1.w) + (a2.w + a3.w);
    if (h == 1) spart[c] = aa;
    __syncthreads();
    if (h == 0) {
        float4 o = spart[c];
        o.x += aa.x; o.y += aa.y; o.z += aa.z; o.w += aa.w;
        *((float4*)(g_cpart + ((size_t)seg*B_ + b)*E_) + c) = o;
    }
}

// ---------------- reduce over 32 segs, float4 ----------------
__global__ void context_reduce_kernel(float* __restrict__ ctx) {
    const int i4 = blockIdx.x*128 + threadIdx.x;     // over B*E/4 = 8192
    float4 s = {0.f, 0.f, 0.f, 0.f};
    #pragma unroll
    for (int seg = 0; seg < SEG_; seg++) {
        float4 p = *((const float4*)(g_cpart + (size_t)seg*B_*E_) + i4);
        s.x += p.x; s.y += p.y; s.z += p.z; s.w += p.w;
    }
    *((float4*)ctx + i4) = s;
}

// ---------------- launch ----------------
extern "C" void kernel_launch(void* const* d_in, const int* in_sizes, int n_in,
                              void* d_out, int out_size)
{
    const float* ahs   = (const float*)d_in[0];   // [B, A]
    const float* mem   = (const float*)d_in[1];   // [B, T, E]
    const float* pmem  = (const float*)d_in[2];   // [B, T, E]
    const float* awc   = (const float*)d_in[3];   // [B, 2, T]
    const int*   mask  = (const int*)d_in[4];     // [B, T] bool -> int32
    const float* Wq    = (const float*)d_in[5];   // [A, A]
    const float* Wm    = (const float*)d_in[6];   // [A, E]
    const float* v     = (const float*)d_in[7];   // [1, A]
    const float* convw = (const float*)d_in[8];   // [NF, 2, K]
    const float* Wl    = (const float*)d_in[9];   // [A, NF]

    float* out_ctx = (float*)d_out;            // [B, E]
    float* out_w   = (float*)d_out + B_*E_;    // [B, T]

    cudaFuncSetAttribute(energies_mma_kernel,
                         cudaFuncAttributeMaxDynamicSharedMemorySize, SMEM_TOTAL);

    prep_kernel<<<196, 256>>>(mask, ahs, Wq, Wm, Wl, convw);
    energies_mma_kernel<<<dim3(T_/64, B_), 256, SMEM_TOTAL>>>(pmem, awc, v);
    softmax_kernel<<<B_, 256>>>(mask, out_w);
    context_part_kernel<<<dim3(SEG_, B_), 256>>>(mem, out_w);
    context_reduce_kernel<<<(B_*E_/4)/128, 128>>>(out_ctx);
}

// round 14
// speedup vs baseline: 1.2826x; 1.1209x over previous
#include <cuda_runtime.h>
#include <cuda_fp16.h>
#include <cstdint>
#include <math.h>

#define B_  64
#define T_  1024
#define E_  512
#define A_  128
#define NF_ 32
#define K_  31
#define SEG_ 32

// ---------------- smem layout for energies kernel (dynamic) ----------------
#define OFF_A0  0
#define OFF_A1  16384
#define OFF_B0  32768
#define OFF_B1  49152
#define OFF_AWC 65536            // 2048 floats (full awc[b])
#define OFF_PQ  73728            // 128 floats
#define OFF_V   74240            // 128 floats
#define OFF_PART 74752           // 512 floats
#define OFF_TIDX 76800           // 128 ints
#define SMEM_TOTAL 77312

// ---------------- scratch ----------------
__device__ float g_pq[B_*A_];
__device__ float g_energies[B_*T_];
__device__ __align__(16) __half g_wmh[A_*E_];     // fp16(Wm)
__device__ __align__(16) __half g_wclh[A_*64];    // fp16(folded Wl@conv_w)
__device__ __align__(16) float g_cpart[SEG_*B_*E_];
__device__ int g_cnt[B_];
__device__ int g_tidx[B_*T_];

// ---------------- helpers ----------------
__device__ __forceinline__ uint32_t smem_u32(const void* p) {
    uint32_t a;
    asm("{ .reg .u64 t; cvta.to.shared.u64 t, %1; cvt.u32.u64 %0, t; }" : "=r"(a) : "l"(p));
    return a;
}
#define STS128(addr, a, b, c, d) \
    asm volatile("st.shared.v4.b32 [%0], {%1,%2,%3,%4};" :: "r"(addr), "r"(a), "r"(b), "r"(c), "r"(d) : "memory")
#define CPASYNC16(dst, src) \
    asm volatile("cp.async.ca.shared.global [%0], [%1], 16;" :: "r"(dst), "l"(src) : "memory")
#define CPCOMMIT() asm volatile("cp.async.commit_group;" ::: "memory")

__device__ __forceinline__ void ldsm_x4(uint32_t (&r)[4], uint32_t addr) {
    asm volatile("ldmatrix.sync.aligned.m8n8.x4.shared.b16 {%0,%1,%2,%3}, [%4];"
        : "=r"(r[0]), "=r"(r[1]), "=r"(r[2]), "=r"(r[3]) : "r"(addr));
}
__device__ __forceinline__ void mma_f16(float (&c)[4], const uint32_t (&a)[4],
                                        uint32_t b0, uint32_t b1) {
    asm volatile("mma.sync.aligned.m16n8k16.row.col.f32.f16.f16.f32 "
        "{%0,%1,%2,%3}, {%4,%5,%6,%7}, {%8,%9}, {%0,%1,%2,%3};"
        : "+f"(c[0]), "+f"(c[1]), "+f"(c[2]), "+f"(c[3])
        : "r"(a[0]), "r"(a[1]), "r"(a[2]), "r"(a[3]), "r"(b0), "r"(b1));
}
__device__ __forceinline__ uint32_t tile_addr(uint32_t base, int row, int kbyte) {
    uint32_t off = (uint32_t)(row*128 + kbyte);
    return base + (off ^ ((off >> 3) & 0x70));
}
__device__ __forceinline__ uint32_t ldsm_addr(uint32_t base, int rb, int kb, int lane) {
    int row = rb + (lane & 15);
    int kbyte = (kb + (lane >> 4)*8)*2;
    return tile_addr(base, row, kbyte);
}
__device__ __forceinline__ uint32_t pack2h(float a, float b) {
    __half2 p = __halves2half2(__float2half_rn(a), __float2half_rn(b));
    return *reinterpret_cast<uint32_t*>(&p);
}
__device__ __forceinline__ float tanh_fast(float x) {
    float e = __expf(fminf(fmaxf(2.f*x, -30.f), 30.f));
    return 1.f - __fdividef(2.f, e + 1.f);
}
__device__ __forceinline__ float locval(const float* s_awc, int tor, int j) {
    if (j >= 62) return 0.f;
    int c = (j >= 31) ? 1 : 0;
    int k = j - c*31;
    int t = tor - 15 + k;
    return (t >= 0 && t < T_) ? s_awc[c*T_ + t] : 0.f;
}

// ---------------- fused prep kernel ----------------
__global__ __launch_bounds__(256)
void prep_kernel(const int* __restrict__ mask,
                 const float* __restrict__ ahs, const float* __restrict__ Wq,
                 const float* __restrict__ Wm,
                 const float* __restrict__ Wl, const float* __restrict__ convw)
{
    __shared__ float smf[6144];
    const int blk = blockIdx.x, tid = threadIdx.x;

    if (blk < 64) {
        const int b = blk;
        int* s1 = (int*)smf;
        int* s2 = s1 + 256;
        int loc[4]; int c = 0;
        #pragma unroll
        for (int q = 0; q < 4; q++) {
            int t = tid*4 + q;
            if (mask[b*T_ + t] == 0) loc[c++] = t;
        }
        s1[tid] = c; __syncthreads();
        int* src = s1; int* dst = s2;
        #pragma unroll
        for (int off = 1; off < 256; off <<= 1) {
            int vv = src[tid];
            if (tid >= off) vv += src[tid - off];
            dst[tid] = vv;
            __syncthreads();
            int* tmp = src; src = dst; dst = tmp;
        }
        int base = src[tid] - c;
        for (int i = 0; i < c; i++) g_tidx[b*T_ + base + i] = loc[i];
        if (tid == 255) g_cnt[b] = src[255];
    } else if (blk < 128) {
        const int b = blk - 64;
        float* sh = smf;
        if (tid < A_) sh[tid] = ahs[b*A_ + tid];
        __syncthreads();
        if (tid < A_) {
            const float* wr = Wq + tid*A_;
            float s = 0.f;
            #pragma unroll 8
            for (int i = 0; i < A_; i++) s += sh[i]*wr[i];
            g_pq[b*A_ + tid] = s;
        }
    } else if (blk < 192) {
        const int i0 = (blk - 128)*1024 + tid*4;
        float4 x = *(const float4*)(Wm + i0);
        uint2 w;
        w.x = pack2h(x.x, x.y);
        w.y = pack2h(x.z, x.w);
        *reinterpret_cast<uint2*>(g_wmh + i0) = w;
    } else {
        const int base_j = (blk - 192)*16;
        float* sWl = smf;                  // [128][32]
        float* sCv = smf + 4096;           // [32][62]
        for (int i = tid; i < A_*NF_; i += 256) sWl[i] = Wl[i];
        for (int i = tid; i < NF_*62; i += 256) sCv[i] = convw[i];
        __syncthreads();
        #pragma unroll
        for (int it = 0; it < 8; it++) {
            int idx = it*256 + tid;
            int jj = idx >> 7, a = idx & 127;
            int j = base_j + jj;
            if (j < 64) {
                float s = 0.f;
                if (j < 62) {
                    #pragma unroll
                    for (int f = 0; f < NF_; f++) s += sWl[a*NF_ + f]*sCv[f*62 + j];
                }
                g_wclh[a*64 + j] = __float2half_rn(s);
            }
        }
    }
}

// ---------------- pipelined HMMA energies: reg-prefetch + 2 CTAs/SM ----------------
__global__ __launch_bounds__(256, 2)
void energies_mma_kernel(const float* __restrict__ pmem,
                         const float* __restrict__ awc,
                         const float* __restrict__ v)
{
    extern __shared__ char smem[];
    const uint32_t sb = smem_u32(smem);
    const int tid = threadIdx.x;
    const int wid = tid >> 5, lane = tid & 31;
    const int b = blockIdx.y, t0 = blockIdx.x*128;
    const int cnt = g_cnt[b];
    if (t0 >= cnt) return;
    const int warp_m = wid & 1, warp_n = wid >> 1;
    const int mb = warp_m*64, nb = warp_n*32;

    float* s_awc  = (float*)(smem + OFF_AWC);
    float* s_pq   = (float*)(smem + OFF_PQ);
    float* s_v    = (float*)(smem + OFF_V);
    float* s_part = (float*)(smem + OFF_PART);
    int*   s_tidx = (int*)(smem + OFF_TIDX);

    // cp.async B(0)
    #pragma unroll
    for (int it = 0; it < 4; it++) {
        int idx = tid + 256*it, r = idx >> 3, g = idx & 7;
        CPASYNC16(tile_addr(sb + OFF_B0, r, g*16), (const void*)(g_wmh + (size_t)r*E_ + g*8));
    }
    CPCOMMIT();

    if (tid < 128) {
        int t = (t0 + tid < cnt) ? g_tidx[b*T_ + t0 + tid] : 0;
        s_tidx[tid] = t;
    }
    for (int i = tid; i < 2*T_; i += 256) s_awc[i] = awc[(size_t)b*2*T_ + i];
    if (tid < A_) { s_pq[tid] = g_pq[b*A_ + tid]; s_v[tid] = v[tid]; }
    __syncthreads();

    const float* rowp[4];
    #pragma unroll
    for (int it = 0; it < 4; it++) {
        int r = (tid >> 3) + 32*it;
        rowp[it] = pmem + ((size_t)b*T_ + s_tidx[r])*E_ + (tid & 7)*8;
    }

    float acc[4][4][4];
    #pragma unroll
    for (int i = 0; i < 4; i++)
        #pragma unroll
        for (int j = 0; j < 4; j++)
            #pragma unroll
            for (int q = 0; q < 4; q++) acc[i][j][q] = 0.f;

    // full register prefetch of A(0)
    float4 pf[8];
    #pragma unroll
    for (int it = 0; it < 4; it++) {
        const float4* p = (const float4*)rowp[it];
        pf[it*2]   = p[0];
        pf[it*2+1] = p[1];
    }

    for (int ch = 0; ch < 9; ch++) {
        const int p = ch & 1;
        const uint32_t baseA = sb + (p ? OFF_A1 : OFF_A0);
        const uint32_t baseB = sb + (p ? OFF_B1 : OFF_B0);

        // ---- convert + STS A(ch) from prefetched registers ----
        if (ch < 8) {
            #pragma unroll
            for (int it = 0; it < 4; it++) {
                int idx = tid + 256*it, r = idx >> 3, g = idx & 7;
                float4 x0 = pf[it*2], x1 = pf[it*2+1];
                STS128(tile_addr(baseA, r, g*16),
                       pack2h(x0.x, x0.y), pack2h(x0.z, x0.w),
                       pack2h(x1.x, x1.y), pack2h(x1.z, x1.w));
            }
        } else {
            const int r = tid >> 1, jb = (tid & 1)*32;
            const int tor = s_tidx[r];
            #pragma unroll
            for (int jj = 0; jj < 32; jj += 8) {
                uint32_t hw[4];
                #pragma unroll
                for (int q = 0; q < 4; q++) {
                    int j0 = jb + jj + 2*q;
                    hw[q] = pack2h(locval(s_awc, tor, j0), locval(s_awc, tor, j0 + 1));
                }
                STS128(tile_addr(baseA, r, (jb + jj)*2), hw[0], hw[1], hw[2], hw[3]);
            }
        }

        // ---- issue next-chunk loads (B via cp.async, A via register prefetch) ----
        if (ch < 8) {
            const uint32_t baseBn = sb + ((ch & 1) ? OFF_B0 : OFF_B1);
            if (ch + 1 < 8) {
                const int e0n = (ch + 1)*64;
                #pragma unroll
                for (int it = 0; it < 4; it++) {
                    int idx = tid + 256*it, r = idx >> 3, g = idx & 7;
                    CPASYNC16(tile_addr(baseBn, r, g*16),
                              (const void*)(g_wmh + (size_t)r*E_ + e0n + g*8));
                }
                CPCOMMIT();
                #pragma unroll
                for (int it = 0; it < 4; it++) {
                    const float4* ptr = (const float4*)(rowp[it] + e0n);
                    pf[it*2]   = ptr[0];
                    pf[it*2+1] = ptr[1];
                }
            } else {
                #pragma unroll
                for (int it = 0; it < 4; it++) {
                    int idx = tid + 256*it, r = idx >> 3, g = idx & 7;
                    CPASYNC16(tile_addr(baseBn, r, g*16),
                              (const void*)(g_wclh + (size_t)r*64 + g*8));
                }
                CPCOMMIT();
            }
            asm volatile("cp.async.wait_group 1;" ::: "memory");
        } else {
            asm volatile("cp.async.wait_group 0;" ::: "memory");
        }
        __syncthreads();

        // ---- MMA: 4 k16 steps ----
        #pragma unroll
        for (int ks = 0; ks < 4; ks++) {
            const int kb = ks*16;
            uint32_t ah[4][4], bf[2][4];
            #pragma unroll
            for (int i = 0; i < 4; i++)
                ldsm_x4(ah[i], ldsm_addr(baseA, mb + 16*i, kb, lane));
            #pragma unroll
            for (int j2 = 0; j2 < 2; j2++)
                ldsm_x4(bf[j2], ldsm_addr(baseB, nb + 16*j2, kb, lane));
            #pragma unroll
            for (int i = 0; i < 4; i++) {
                #pragma unroll
                for (int j = 0; j < 4; j++) {
                    const int j2 = j >> 1, jo = j & 1;
                    mma_f16(acc[i][j], ah[i], bf[j2][jo], bf[j2][jo+2]);
                }
            }
        }
        if (ch < 8) __syncthreads();
    }

    // ---- epilogue ----
    #pragma unroll
    for (int i = 0; i < 4; i++) {
        #pragma unroll
        for (int half = 0; half < 2; half++) {
            float s = 0.f;
            #pragma unroll
            for (int j = 0; j < 4; j++) {
                const int a0 = nb + j*8 + (lane & 3)*2;
                float x0 = acc[i][j][half*2+0] + s_pq[a0];
                float x1 = acc[i][j][half*2+1] + s_pq[a0+1];
                s += s_v[a0]*tanh_fast(x0) + s_v[a0+1]*tanh_fast(x1);
            }
            s += __shfl_xor_sync(0xffffffffu, s, 1);
            s += __shfl_xor_sync(0xffffffffu, s, 2);
            if ((lane & 3) == 0) {
                int row = mb + i*16 + (lane >> 2) + half*8;
                s_part[row*4 + warp_n] = s;
            }
        }
    }
    __syncthreads();
    if (tid < 128 && t0 + tid < cnt) {
        const float* pp = s_part + tid*4;
        g_energies[(size_t)b*T_ + s_tidx[tid]] = (pp[0] + pp[1]) + (pp[2] + pp[3]);
    }
}

// ---------------- masked softmax over T ----------------
__global__ void softmax_kernel(const int* __restrict__ mask, float* __restrict__ wout) {
    const int b = blockIdx.x, tid = threadIdx.x;
    __shared__ float red[256];
    float e[4];
    float mx = -INFINITY;
    #pragma unroll
    for (int q = 0; q < 4; q++) {
        int t = tid + 256*q;
        float ev = g_energies[b*T_ + t];
        if (mask[b*T_ + t] != 0) ev = -INFINITY;
        e[q] = ev;
        mx = fmaxf(mx, ev);
    }
    red[tid] = mx; __syncthreads();
    for (int s = 128; s > 0; s >>= 1) {
        if (tid < s) red[tid] = fmaxf(red[tid], red[tid + s]);
        __syncthreads();
    }
    const float m = red[0];
    __syncthreads();
    float ex[4], sum = 0.f;
    #pragma unroll
    for (int q = 0; q < 4; q++) {
        ex[q] = (e[q] == -INFINITY) ? 0.f : expf(e[q] - m);
        sum += ex[q];
    }
    red[tid] = sum; __syncthreads();
    for (int s = 128; s > 0; s >>= 1) {
        if (tid < s) red[tid] += red[tid + s];
        __syncthreads();
    }
    const float inv = 1.f / red[0];
    #pragma unroll
    for (int q = 0; q < 4; q++) wout[b*T_ + tid + 256*q] = ex[q]*inv;
}

// ---------------- context: 32 segs, full E row per CTA, LDG.64 (R10 form) ----------------
__global__ __launch_bounds__(256)
void context_part_kernel(const float* __restrict__ mem,
                         const float* __restrict__ w)
{
    __shared__ float sw[32];
    __shared__ int sti[32];
    const int seg = blockIdx.x, b = blockIdx.y;
    const int tid = threadIdx.x;
    const int cnt = g_cnt[b];
    const int base = seg*32;

    if (tid < 32) {
        int ci = base + tid;
        int t = (ci < cnt) ? g_tidx[b*T_ + ci] : 0;
        sti[tid] = t;
        sw[tid] = (ci < cnt) ? w[b*T_ + t] : 0.f;
    }
    __syncthreads();

    int rows = cnt - base;
    rows = rows < 0 ? 0 : (rows > 32 ? 32 : rows);

    const float2* mb = (const float2*)(mem + (size_t)b*T_*E_) + tid;
    float2 a0 = {0.f, 0.f}, a1 = {0.f, 0.f}, a2 = {0.f, 0.f}, a3 = {0.f, 0.f};
    int t = 0;
    for (; t + 8 <= rows; t += 8) {
        float2 m0 = mb[(size_t)sti[t  ]*(E_/2)];
        float2 m1 = mb[(size_t)sti[t+1]*(E_/2)];
        float2 m2 = mb[(size_t)sti[t+2]*(E_/2)];
        float2 m3 = mb[(size_t)sti[t+3]*(E_/2)];
        float2 m4 = mb[(size_t)sti[t+4]*(E_/2)];
        float2 m5 = mb[(size_t)sti[t+5]*(E_/2)];
        float2 m6 = mb[(size_t)sti[t+6]*(E_/2)];
        float2 m7 = mb[(size_t)sti[t+7]*(E_/2)];
        a0.x += sw[t  ]*m0.x; a0.y += sw[t  ]*m0.y;
        a1.x += sw[t+1]*m1.x; a1.y += sw[t+1]*m1.y;
        a2.x += sw[t+2]*m2.x; a2.y += sw[t+2]*m2.y;
        a3.x += sw[t+3]*m3.x; a3.y += sw[t+3]*m3.y;
        a0.x += sw[t+4]*m4.x; a0.y += sw[t+4]*m4.y;
        a1.x += sw[t+5]*m5.x; a1.y += sw[t+5]*m5.y;
        a2.x += sw[t+6]*m6.x; a2.y += sw[t+6]*m6.y;
        a3.x += sw[t+7]*m7.x; a3.y += sw[t+7]*m7.y;
    }
    for (; t < rows; t++) {
        float2 m0 = mb[(size_t)sti[t]*(E_/2)];
        a0.x += sw[t]*m0.x; a0.y += sw[t]*m0.y;
    }
    float2 r;
    r.x = (a0.x + a1.x) + (a2.x + a3.x);
    r.y = (a0.y + a1.y) + (a2.y + a3.y);
    *((float2*)(g_cpart + ((size_t)seg*B_ + b)*E_) + tid) = r;
}

// ---------------- reduce over 32 segs, float4 ----------------
__global__ void context_reduce_kernel(float* __restrict__ ctx) {
    const int i4 = blockIdx.x*256 + threadIdx.x;     // over B*E/4
    float4 s = {0.f, 0.f, 0.f, 0.f};
    #pragma unroll
    for (int seg = 0; seg < SEG_; seg++) {
        float4 p = *((const float4*)(g_cpart + (size_t)seg*B_*E_) + i4);
        s.x += p.x; s.y += p.y; s.z += p.z; s.w += p.w;
    }
    *((float4*)ctx + i4) = s;
}

// ---------------- launch ----------------
extern "C" void kernel_launch(void* const* d_in, const int* in_sizes, int n_in,
                              void* d_out, int out_size)
{
    const float* ahs   = (const float*)d_in[0];   // [B, A]
    const float* mem   = (const float*)d_in[1];   // [B, T, E]
    const float* pmem  = (const float*)d_in[2];   // [B, T, E]
    const float* awc   = (const float*)d_in[3];   // [B, 2, T]
    const int*   mask  = (const int*)d_in[4];     // [B, T] bool -> int32
    const float* Wq    = (const float*)d_in[5];   // [A, A]
    const float* Wm    = (const float*)d_in[6];   // [A, E]
    const float* v     = (const float*)d_in[7];   // [1, A]
    const float* convw = (const float*)d_in[8];   // [NF, 2, K]
    const float* Wl    = (const float*)d_in[9];   // [A, NF]

    float* out_ctx = (float*)d_out;            // [B, E]
    float* out_w   = (float*)d_out + B_*E_;    // [B, T]

    cudaFuncSetAttribute(energies_mma_kernel,
                         cudaFuncAttributeMaxDynamicSharedMemorySize, SMEM_TOTAL);

    prep_kernel<<<196, 256>>>(mask, ahs, Wq, Wm, Wl, convw);
    energies_mma_kernel<<<dim3(T_/128, B_), 256, SMEM_TOTAL>>>(pmem, awc, v);
    softmax_kernel<<<B_, 256>>>(mask, out_w);
    context_part_kernel<<<dim3(SEG_, B_), 256>>>(mem, out_w);
    context_reduce_kernel<<<(B_*E_/4)/256, 256>>>(out_ctx);
}

// round 15
// speedup vs baseline: 1.3269x; 1.0345x over previous
#include <cuda_runtime.h>
#include <cuda_fp16.h>
#include <cstdint>
#include <math.h>

#define B_  64
#define T_  1024
#define E_  512
#define A_  128
#define NF_ 32
#define K_  31
#define SEG_ 32

// ---------------- smem layout for energies kernel (dynamic) ----------------
#define OFF_A0  0
#define OFF_A1  16384
#define OFF_B0  32768
#define OFF_B1  49152
#define OFF_AWC 65536            // 2048 floats (full awc[b])
#define OFF_PQ  73728            // 128 floats
#define OFF_V   74240            // 128 floats
#define OFF_PART 74752           // 512 floats
#define OFF_TIDX 76800           // 128 ints
#define SMEM_TOTAL 77312

// ---------------- scratch ----------------
__device__ float g_pq[B_*A_];
__device__ float g_energies[B_*T_];
__device__ __align__(16) __half g_wmh[A_*E_];     // fp16(Wm)
__device__ __align__(16) __half g_wclh[A_*64];    // fp16(folded Wl@conv_w)
__device__ __align__(16) float g_cpart[SEG_*B_*E_];
__device__ int g_cnt[B_];
__device__ int g_tidx[B_*T_];

// ---------------- helpers ----------------
__device__ __forceinline__ uint32_t smem_u32(const void* p) {
    uint32_t a;
    asm("{ .reg .u64 t; cvta.to.shared.u64 t, %1; cvt.u32.u64 %0, t; }" : "=r"(a) : "l"(p));
    return a;
}
#define STS128(addr, a, b, c, d) \
    asm volatile("st.shared.v4.b32 [%0], {%1,%2,%3,%4};" :: "r"(addr), "r"(a), "r"(b), "r"(c), "r"(d) : "memory")
#define CPASYNC16(dst, src) \
    asm volatile("cp.async.ca.shared.global [%0], [%1], 16;" :: "r"(dst), "l"(src) : "memory")
#define CPASYNC16CG(dst, src) \
    asm volatile("cp.async.cg.shared.global [%0], [%1], 16;" :: "r"(dst), "l"(src) : "memory")
#define CPCOMMIT() asm volatile("cp.async.commit_group;" ::: "memory")

__device__ __forceinline__ void ldsm_x4(uint32_t (&r)[4], uint32_t addr) {
    asm volatile("ldmatrix.sync.aligned.m8n8.x4.shared.b16 {%0,%1,%2,%3}, [%4];"
        : "=r"(r[0]), "=r"(r[1]), "=r"(r[2]), "=r"(r[3]) : "r"(addr));
}
__device__ __forceinline__ void mma_f16(float (&c)[4], const uint32_t (&a)[4],
                                        uint32_t b0, uint32_t b1) {
    asm volatile("mma.sync.aligned.m16n8k16.row.col.f32.f16.f16.f32 "
        "{%0,%1,%2,%3}, {%4,%5,%6,%7}, {%8,%9}, {%0,%1,%2,%3};"
        : "+f"(c[0]), "+f"(c[1]), "+f"(c[2]), "+f"(c[3])
        : "r"(a[0]), "r"(a[1]), "r"(a[2]), "r"(a[3]), "r"(b0), "r"(b1));
}
__device__ __forceinline__ uint32_t tile_addr(uint32_t base, int row, int kbyte) {
    uint32_t off = (uint32_t)(row*128 + kbyte);
    return base + (off ^ ((off >> 3) & 0x70));
}
__device__ __forceinline__ uint32_t ldsm_addr(uint32_t base, int rb, int kb, int lane) {
    int row = rb + (lane & 15);
    int kbyte = (kb + (lane >> 4)*8)*2;
    return tile_addr(base, row, kbyte);
}
__device__ __forceinline__ uint32_t pack2h(float a, float b) {
    __half2 p = __halves2half2(__float2half_rn(a), __float2half_rn(b));
    return *reinterpret_cast<uint32_t*>(&p);
}
__device__ __forceinline__ float tanh_fast(float x) {
    float e = __expf(fminf(fmaxf(2.f*x, -30.f), 30.f));
    return 1.f - __fdividef(2.f, e + 1.f);
}
__device__ __forceinline__ float locval(const float* s_awc, int tor, int j) {
    if (j >= 62) return 0.f;
    int c = (j >= 31) ? 1 : 0;
    int k = j - c*31;
    int t = tor - 15 + k;
    return (t >= 0 && t < T_) ? s_awc[c*T_ + t] : 0.f;
}

// ---------------- fused prep kernel ----------------
__global__ __launch_bounds__(256)
void prep_kernel(const int* __restrict__ mask,
                 const float* __restrict__ ahs, const float* __restrict__ Wq,
                 const float* __restrict__ Wm,
                 const float* __restrict__ Wl, const float* __restrict__ convw)
{
    __shared__ float smf[6144];
    const int blk = blockIdx.x, tid = threadIdx.x;

    if (blk < 64) {
        const int b = blk;
        int* s1 = (int*)smf;
        int* s2 = s1 + 256;
        int loc[4]; int c = 0;
        #pragma unroll
        for (int q = 0; q < 4; q++) {
            int t = tid*4 + q;
            if (mask[b*T_ + t] == 0) loc[c++] = t;
        }
        s1[tid] = c; __syncthreads();
        int* src = s1; int* dst = s2;
        #pragma unroll
        for (int off = 1; off < 256; off <<= 1) {
            int vv = src[tid];
            if (tid >= off) vv += src[tid - off];
            dst[tid] = vv;
            __syncthreads();
            int* tmp = src; src = dst; dst = tmp;
        }
        int base = src[tid] - c;
        for (int i = 0; i < c; i++) g_tidx[b*T_ + base + i] = loc[i];
        if (tid == 255) g_cnt[b] = src[255];
    } else if (blk < 128) {
        const int b = blk - 64;
        float* sh = smf;
        if (tid < A_) sh[tid] = ahs[b*A_ + tid];
        __syncthreads();
        if (tid < A_) {
            const float* wr = Wq + tid*A_;
            float s = 0.f;
            #pragma unroll 8
            for (int i = 0; i < A_; i++) s += sh[i]*wr[i];
            g_pq[b*A_ + tid] = s;
        }
    } else if (blk < 192) {
        const int i0 = (blk - 128)*1024 + tid*4;
        float4 x = *(const float4*)(Wm + i0);
        uint2 w;
        w.x = pack2h(x.x, x.y);
        w.y = pack2h(x.z, x.w);
        *reinterpret_cast<uint2*>(g_wmh + i0) = w;
    } else {
        const int base_j = (blk - 192)*16;
        float* sWl = smf;                  // [128][32]
        float* sCv = smf + 4096;           // [32][62]
        for (int i = tid; i < A_*NF_; i += 256) sWl[i] = Wl[i];
        for (int i = tid; i < NF_*62; i += 256) sCv[i] = convw[i];
        __syncthreads();
        #pragma unroll
        for (int it = 0; it < 8; it++) {
            int idx = it*256 + tid;
            int jj = idx >> 7, a = idx & 127;
            int j = base_j + jj;
            if (j < 64) {
                float s = 0.f;
                if (j < 62) {
                    #pragma unroll
                    for (int f = 0; f < NF_; f++) s += sWl[a*NF_ + f]*sCv[f*62 + j];
                }
                g_wclh[a*64 + j] = __float2half_rn(s);
            }
        }
    }
}

// ---------------- pipelined HMMA energies: reg-prefetch + 2 CTAs/SM ----------------
__global__ __launch_bounds__(256, 2)
void energies_mma_kernel(const float* __restrict__ pmem,
                         const float* __restrict__ awc,
                         const float* __restrict__ v)
{
    extern __shared__ char smem[];
    const uint32_t sb = smem_u32(smem);
    const int tid = threadIdx.x;
    const int wid = tid >> 5, lane = tid & 31;
    const int b = blockIdx.y, t0 = blockIdx.x*128;
    const int cnt = g_cnt[b];
    if (t0 >= cnt) return;
    const int warp_m = wid & 1, warp_n = wid >> 1;
    const int mb = warp_m*64, nb = warp_n*32;

    float* s_awc  = (float*)(smem + OFF_AWC);
    float* s_pq   = (float*)(smem + OFF_PQ);
    float* s_v    = (float*)(smem + OFF_V);
    float* s_part = (float*)(smem + OFF_PART);
    int*   s_tidx = (int*)(smem + OFF_TIDX);

    // cp.async B(0) (L2-only: B is streamed once into smem, shared via L2)
    #pragma unroll
    for (int it = 0; it < 4; it++) {
        int idx = tid + 256*it, r = idx >> 3, g = idx & 7;
        CPASYNC16CG(tile_addr(sb + OFF_B0, r, g*16), (const void*)(g_wmh + (size_t)r*E_ + g*8));
    }
    CPCOMMIT();

    if (tid < 128) {
        int t = (t0 + tid < cnt) ? g_tidx[b*T_ + t0 + tid] : 0;
        s_tidx[tid] = t;
    }
    for (int i = tid; i < 2*T_; i += 256) s_awc[i] = awc[(size_t)b*2*T_ + i];
    if (tid < A_) { s_pq[tid] = g_pq[b*A_ + tid]; s_v[tid] = v[tid]; }
    __syncthreads();

    const float* rowp[4];
    #pragma unroll
    for (int it = 0; it < 4; it++) {
        int r = (tid >> 3) + 32*it;
        rowp[it] = pmem + ((size_t)b*T_ + s_tidx[r])*E_ + (tid & 7)*8;
    }

    float acc[4][4][4];
    #pragma unroll
    for (int i = 0; i < 4; i++)
        #pragma unroll
        for (int j = 0; j < 4; j++)
            #pragma unroll
            for (int q = 0; q < 4; q++) acc[i][j][q] = 0.f;

    // full register prefetch of A(0)
    float4 pf[8];
    #pragma unroll
    for (int it = 0; it < 4; it++) {
        const float4* p = (const float4*)rowp[it];
        pf[it*2]   = p[0];
        pf[it*2+1] = p[1];
    }

    for (int ch = 0; ch < 9; ch++) {
        const int p = ch & 1;
        const uint32_t baseA = sb + (p ? OFF_A1 : OFF_A0);
        const uint32_t baseB = sb + (p ? OFF_B1 : OFF_B0);

        // ---- convert + STS A(ch) from prefetched registers ----
        if (ch < 8) {
            #pragma unroll
            for (int it = 0; it < 4; it++) {
                int idx = tid + 256*it, r = idx >> 3, g = idx & 7;
                float4 x0 = pf[it*2], x1 = pf[it*2+1];
                STS128(tile_addr(baseA, r, g*16),
                       pack2h(x0.x, x0.y), pack2h(x0.z, x0.w),
                       pack2h(x1.x, x1.y), pack2h(x1.z, x1.w));
            }
        } else {
            const int r = tid >> 1, jb = (tid & 1)*32;
            const int tor = s_tidx[r];
            #pragma unroll
            for (int jj = 0; jj < 32; jj += 8) {
                uint32_t hw[4];
                #pragma unroll
                for (int q = 0; q < 4; q++) {
                    int j0 = jb + jj + 2*q;
                    hw[q] = pack2h(locval(s_awc, tor, j0), locval(s_awc, tor, j0 + 1));
                }
                STS128(tile_addr(baseA, r, (jb + jj)*2), hw[0], hw[1], hw[2], hw[3]);
            }
        }

        // ---- issue next-chunk loads (B via cp.async.cg, A via register prefetch) ----
        if (ch < 8) {
            const uint32_t baseBn = sb + ((ch & 1) ? OFF_B0 : OFF_B1);
            if (ch + 1 < 8) {
                const int e0n = (ch + 1)*64;
                #pragma unroll
                for (int it = 0; it < 4; it++) {
                    int idx = tid + 256*it, r = idx >> 3, g = idx & 7;
                    CPASYNC16CG(tile_addr(baseBn, r, g*16),
                                (const void*)(g_wmh + (size_t)r*E_ + e0n + g*8));
                }
                CPCOMMIT();
                #pragma unroll
                for (int it = 0; it < 4; it++) {
                    const float4* ptr = (const float4*)(rowp[it] + e0n);
                    pf[it*2]   = ptr[0];
                    pf[it*2+1] = ptr[1];
                }
            } else {
                #pragma unroll
                for (int it = 0; it < 4; it++) {
                    int idx = tid + 256*it, r = idx >> 3, g = idx & 7;
                    CPASYNC16CG(tile_addr(baseBn, r, g*16),
                                (const void*)(g_wclh + (size_t)r*64 + g*8));
                }
                CPCOMMIT();
            }
            asm volatile("cp.async.wait_group 1;" ::: "memory");
        } else {
            asm volatile("cp.async.wait_group 0;" ::: "memory");
        }
        __syncthreads();

        // ---- MMA: 4 k16 steps ----
        #pragma unroll
        for (int ks = 0; ks < 4; ks++) {
            const int kb = ks*16;
            uint32_t ah[4][4], bf[2][4];
            #pragma unroll
            for (int i = 0; i < 4; i++)
                ldsm_x4(ah[i], ldsm_addr(baseA, mb + 16*i, kb, lane));
            #pragma unroll
            for (int j2 = 0; j2 < 2; j2++)
                ldsm_x4(bf[j2], ldsm_addr(baseB, nb + 16*j2, kb, lane));
            #pragma unroll
            for (int i = 0; i < 4; i++) {
                #pragma unroll
                for (int j = 0; j < 4; j++) {
                    const int j2 = j >> 1, jo = j & 1;
                    mma_f16(acc[i][j], ah[i], bf[j2][jo], bf[j2][jo+2]);
                }
            }
        }
        if (ch < 8) __syncthreads();
    }

    // ---- epilogue ----
    #pragma unroll
    for (int i = 0; i < 4; i++) {
        #pragma unroll
        for (int half = 0; half < 2; half++) {
            float s = 0.f;
            #pragma unroll
            for (int j = 0; j < 4; j++) {
                const int a0 = nb + j*8 + (lane & 3)*2;
                float x0 = acc[i][j][half*2+0] + s_pq[a0];
                float x1 = acc[i][j][half*2+1] + s_pq[a0+1];
                s += s_v[a0]*tanh_fast(x0) + s_v[a0+1]*tanh_fast(x1);
            }
            s += __shfl_xor_sync(0xffffffffu, s, 1);
            s += __shfl_xor_sync(0xffffffffu, s, 2);
            if ((lane & 3) == 0) {
                int row = mb + i*16 + (lane >> 2) + half*8;
                s_part[row*4 + warp_n] = s;
            }
        }
    }
    __syncthreads();
    if (tid < 128 && t0 + tid < cnt) {
        const float* pp = s_part + tid*4;
        g_energies[(size_t)b*T_ + s_tidx[tid]] = (pp[0] + pp[1]) + (pp[2] + pp[3]);
    }
}

// ---------------- masked softmax over T: 1024 threads, shuffle reductions ----------------
__global__ __launch_bounds__(1024)
void softmax_kernel(const int* __restrict__ mask, float* __restrict__ wout) {
    const int b = blockIdx.x, tid = threadIdx.x;
    const int lane = tid & 31, w = tid >> 5;
    __shared__ float red[32];

    float ev = g_energies[b*T_ + tid];
    const bool msk = (mask[b*T_ + tid] != 0);
    if (msk) ev = -INFINITY;

    // block max
    float mx = ev;
    #pragma unroll
    for (int o = 16; o > 0; o >>= 1) mx = fmaxf(mx, __shfl_xor_sync(0xffffffffu, mx, o));
    if (lane == 0) red[w] = mx;
    __syncthreads();
    if (w == 0) {
        float m2 = red[lane];
        #pragma unroll
        for (int o = 16; o > 0; o >>= 1) m2 = fmaxf(m2, __shfl_xor_sync(0xffffffffu, m2, o));
        red[lane] = m2;
    }
    __syncthreads();
    const float m = red[0];

    // block sum of exp
    float ex = msk ? 0.f : expf(ev - m);
    float sum = ex;
    #pragma unroll
    for (int o = 16; o > 0; o >>= 1) sum += __shfl_xor_sync(0xffffffffu, sum, o);
    __syncthreads();
    if (lane == 0) red[w] = sum;
    __syncthreads();
    if (w == 0) {
        float s2 = red[lane];
        #pragma unroll
        for (int o = 16; o > 0; o >>= 1) s2 += __shfl_xor_sync(0xffffffffu, s2, o);
        red[lane] = s2;
    }
    __syncthreads();
    wout[b*T_ + tid] = ex / red[0];
}

// ---------------- context: 32 segs, full E row per CTA, LDG.64 (R10 form) ----------------
__global__ __launch_bounds__(256)
void context_part_kernel(const float* __restrict__ mem,
                         const float* __restrict__ w)
{
    __shared__ float sw[32];
    __shared__ int sti[32];
    const int seg = blockIdx.x, b = blockIdx.y;
    const int tid = threadIdx.x;
    const int cnt = g_cnt[b];
    const int base = seg*32;

    if (tid < 32) {
        int ci = base + tid;
        int t = (ci < cnt) ? g_tidx[b*T_ + ci] : 0;
        sti[tid] = t;
        sw[tid] = (ci < cnt) ? w[b*T_ + t] : 0.f;
    }
    __syncthreads();

    int rows = cnt - base;
    rows = rows < 0 ? 0 : (rows > 32 ? 32 : rows);

    const float2* mb = (const float2*)(mem + (size_t)b*T_*E_) + tid;
    float2 a0 = {0.f, 0.f}, a1 = {0.f, 0.f}, a2 = {0.f, 0.f}, a3 = {0.f, 0.f};
    int t = 0;
    for (; t + 8 <= rows; t += 8) {
        float2 m0 = mb[(size_t)sti[t  ]*(E_/2)];
        float2 m1 = mb[(size_t)sti[t+1]*(E_/2)];
        float2 m2 = mb[(size_t)sti[t+2]*(E_/2)];
        float2 m3 = mb[(size_t)sti[t+3]*(E_/2)];
        float2 m4 = mb[(size_t)sti[t+4]*(E_/2)];
        float2 m5 = mb[(size_t)sti[t+5]*(E_/2)];
        float2 m6 = mb[(size_t)sti[t+6]*(E_/2)];
        float2 m7 = mb[(size_t)sti[t+7]*(E_/2)];
        a0.x += sw[t  ]*m0.x; a0.y += sw[t  ]*m0.y;
        a1.x += sw[t+1]*m1.x; a1.y += sw[t+1]*m1.y;
        a2.x += sw[t+2]*m2.x; a2.y += sw[t+2]*m2.y;
        a3.x += sw[t+3]*m3.x; a3.y += sw[t+3]*m3.y;
        a0.x += sw[t+4]*m4.x; a0.y += sw[t+4]*m4.y;
        a1.x += sw[t+5]*m5.x; a1.y += sw[t+5]*m5.y;
        a2.x += sw[t+6]*m6.x; a2.y += sw[t+6]*m6.y;
        a3.x += sw[t+7]*m7.x; a3.y += sw[t+7]*m7.y;
    }
    for (; t < rows; t++) {
        float2 m0 = mb[(size_t)sti[t]*(E_/2)];
        a0.x += sw[t]*m0.x; a0.y += sw[t]*m0.y;
    }
    float2 r;
    r.x = (a0.x + a1.x) + (a2.x + a3.x);
    r.y = (a0.y + a1.y) + (a2.y + a3.y);
    *((float2*)(g_cpart + ((size_t)seg*B_ + b)*E_) + tid) = r;
}

// ---------------- reduce over 32 segs, float4, 256 CTAs ----------------
__global__ __launch_bounds__(128)
void context_reduce_kernel(float* __restrict__ ctx) {
    const int i4 = blockIdx.x*32 + (threadIdx.x & 31);   // over B*E/4 = 8192, 256 blocks
    const int sg = threadIdx.x >> 5;                     // 4 seg-groups per block
    __shared__ float4 sp[3][32];
    float4 s = {0.f, 0.f, 0.f, 0.f};
    #pragma unroll
    for (int q = 0; q < SEG_/4; q++) {
        int seg = sg*(SEG_/4) + q;
        float4 p = *((const float4*)(g_cpart + (size_t)seg*B_*E_) + i4);
        s.x += p.x; s.y += p.y; s.z += p.z; s.w += p.w;
    }
    if (sg > 0) sp[sg-1][threadIdx.x & 31] = s;
    __syncthreads();
    if (sg == 0) {
        #pragma unroll
        for (int q = 0; q < 3; q++) {
            float4 p = sp[q][threadIdx.x];
            s.x += p.x; s.y += p.y; s.z += p.z; s.w += p.w;
        }
        *((float4*)ctx + i4) = s;
    }
}

// ---------------- launch ----------------
extern "C" void kernel_launch(void* const* d_in, const int* in_sizes, int n_in,
                              void* d_out, int out_size)
{
    const float* ahs   = (const float*)d_in[0];   // [B, A]
    const float* mem   = (const float*)d_in[1];   // [B, T, E]
    const float* pmem  = (const float*)d_in[2];   // [B, T, E]
    const float* awc   = (const float*)d_in[3];   // [B, 2, T]
    const int*   mask  = (const int*)d_in[4];     // [B, T] bool -> int32
    const float* Wq    = (const float*)d_in[5];   // [A, A]
    const float* Wm    = (const float*)d_in[6];   // [A, E]
    const float* v     = (const float*)d_in[7];   // [1, A]
    const float* convw = (const float*)d_in[8];   // [NF, 2, K]
    const float* Wl    = (const float*)d_in[9];   // [A, NF]

    float* out_ctx = (float*)d_out;            // [B, E]
    float* out_w   = (float*)d_out + B_*E_;    // [B, T]

    cudaFuncSetAttribute(energies_mma_kernel,
                         cudaFuncAttributeMaxDynamicSharedMemorySize, SMEM_TOTAL);

    prep_kernel<<<196, 256>>>(mask, ahs, Wq, Wm, Wl, convw);
    energies_mma_kernel<<<dim3(T_/128, B_), 256, SMEM_TOTAL>>>(pmem, awc, v);
    softmax_kernel<<<B_, 1024>>>(mask, out_w);
    context_part_kernel<<<dim3(SEG_, B_), 256>>>(mem, out_w);
    context_reduce_kernel<<<256, 128>>>(out_ctx);
}